// round 1
// baseline (speedup 1.0000x reference)
#include <cuda_runtime.h>
#include <cstdint>

#define NN 16
#define KK 4
#define BB 16384
#define DD 64
#define FINAL_ID 15

// packed spike masks: one 64-bit mask per (node,row): bit d = (s_prev[n,b,d] != 0)
__device__ uint2 g_packed[NN * BB];

// ---------------------------------------------------------------------------
// Kernel 0: pack s_prev (binary 0/1 floats) into bitmasks. HBM-bound, ~64MB read.
// ---------------------------------------------------------------------------
__global__ void pack_kernel(const float* __restrict__ s_prev) {
    const int ROWS_PER_WARP = 8;
    int warp = (blockIdx.x * blockDim.x + threadIdx.x) >> 5;
    int lane = threadIdx.x & 31;
    int row0 = warp * ROWS_PER_WARP;
    #pragma unroll
    for (int r = 0; r < ROWS_PER_WARP; r++) {
        int row = row0 + r;                        // row in [0, NN*BB)
        float v0 = s_prev[(size_t)row * DD + lane];
        float v1 = s_prev[(size_t)row * DD + 32 + lane];
        unsigned lo = __ballot_sync(0xffffffffu, v0 != 0.0f);
        unsigned hi = __ballot_sync(0xffffffffu, v1 != 0.0f);
        if (lane == 0) g_packed[row] = make_uint2(lo, hi);
    }
}

// ---------------------------------------------------------------------------
// Kernel 1: fused gather + per-node Dense + LIF update.
// grid = (NN, BB/128), block = 256 threads (8 warps x 16 rows each).
// Thread owns output dims {2*lane, 2*lane+1} of its warp's current row.
// ---------------------------------------------------------------------------
__global__ __launch_bounds__(256, 2)
void snn_fused_kernel(const float* __restrict__ inputs,
                      const float* __restrict__ u,
                      const float* __restrict__ i_syn,
                      const float* __restrict__ W,
                      const float* __restrict__ bias,
                      const int*   __restrict__ conn,
                      float* __restrict__ out) {
    extern __shared__ float Wsh[];                 // [320][64] = 80 KB

    const int n    = blockIdx.x;
    const int tile = blockIdx.y;
    const int tid  = threadIdx.x;
    const int lane = tid & 31;
    const int warp = tid >> 5;

    // cooperative load of W[n] (320x64 floats) into smem, float4 vectorized
    {
        const float4* Wg  = (const float4*)(W + (size_t)n * 320 * 64);
        float4*       Ws4 = (float4*)Wsh;
        #pragma unroll
        for (int i = 0; i < 20; i++)
            Ws4[tid + i * 256] = Wg[tid + i * 256];
    }

    int src[KK];
    #pragma unroll
    for (int k = 0; k < KK; k++) src[k] = conn[n * KK + k];

    float2 bv = *(const float2*)(bias + n * DD + 2 * lane);
    __syncthreads();

    // output layout: [out (B*D)] [s_new (N*B*D)] [u_out (N*B*D)] [i_new (N*B*D)]
    float* s_out = out + (size_t)BB * DD;
    float* u_out = s_out + (size_t)NN * BB * DD;
    float* i_out = u_out + (size_t)NN * BB * DD;

    const int rowbase = tile * 128 + warp * 16;

    for (int r = 0; r < 16; r++) {
        const int b = rowbase + r;

        // external input for this row (heavily L1/L2 reused across nodes)
        float in0 = inputs[b * DD + lane];
        float in1 = inputs[b * DD + 32 + lane];

        // packed predecessor spike masks (broadcast loads)
        uint2 m[KK];
        #pragma unroll
        for (int k = 0; k < KK; k++) m[k] = g_packed[src[k] * BB + b];

        // LIF state loads issued early to overlap with the dense loop
        const size_t base = ((size_t)n * BB + b) * DD + 2 * lane;
        float2 uu = *(const float2*)(u + base);
        float2 is = *(const float2*)(i_syn + base);

        float2 acc = bv;

        // dense block: inputs(64) @ W[256:320, :]
        #pragma unroll
        for (int d = 0; d < 64; d++) {
            float v = __shfl_sync(0xffffffffu, (d < 32) ? in0 : in1, d & 31);
            float2 w = *(const float2*)(Wsh + (256 + d) * 64 + 2 * lane);
            acc.x = fmaf(v, w.x, acc.x);
            acc.y = fmaf(v, w.y, acc.y);
        }

        // sparse block: sum W rows where spike bit set (spikes are exactly 1.0)
        #pragma unroll
        for (int j = 0; j < 8; j++) {
            unsigned mm = (j & 1) ? m[j >> 1].y : m[j >> 1].x;
            while (mm) {
                int bit = __ffs(mm) - 1;
                mm &= mm - 1;
                float2 w = *(const float2*)(Wsh + (j * 32 + bit) * 64 + 2 * lane);
                acc.x += w.x;
                acc.y += w.y;
            }
        }

        // LIF update (fp32, scalar literals matching jnp weak-typed constants)
        float2 inew, unew, sv, uo;
        inew.x = fmaf(0.9f, is.x, acc.x);
        inew.y = fmaf(0.9f, is.y, acc.y);
        unew.x = fmaf(0.95f, uu.x, 0.05f * inew.x);
        unew.y = fmaf(0.95f, uu.y, 0.05f * inew.y);
        sv.x = (unew.x - 1.0f > 0.0f) ? 1.0f : 0.0f;
        sv.y = (unew.y - 1.0f > 0.0f) ? 1.0f : 0.0f;
        uo.x = (sv.x > 0.5f) ? 0.0f : unew.x;
        uo.y = (sv.y > 0.5f) ? 0.0f : unew.y;

        *(float2*)(s_out + base) = sv;
        *(float2*)(u_out + base) = uo;
        *(float2*)(i_out + base) = inew;
        if (n == FINAL_ID)
            *(float2*)(out + (size_t)b * DD + 2 * lane) = sv;
    }
}

// ---------------------------------------------------------------------------
extern "C" void kernel_launch(void* const* d_in, const int* in_sizes, int n_in,
                              void* d_out, int out_size) {
    const float* inputs = (const float*)d_in[0];
    const float* u      = (const float*)d_in[1];
    const float* i_syn  = (const float*)d_in[2];
    const float* s_prev = (const float*)d_in[3];
    const float* W      = (const float*)d_in[4];
    const float* bias   = (const float*)d_in[5];
    const int*   conn   = (const int*)d_in[6];
    float* out = (float*)d_out;

    // pack: N*B rows / (8 rows/warp * 8 warps/block) = 4096 blocks
    pack_kernel<<<(NN * BB) / 64, 256>>>(s_prev);

    const int smem = 320 * 64 * sizeof(float);     // 80 KB > 48 KB static limit
    cudaFuncSetAttribute(snn_fused_kernel,
                         cudaFuncAttributeMaxDynamicSharedMemorySize, smem);

    dim3 grid(NN, BB / 128);
    snn_fused_kernel<<<grid, 256, smem>>>(inputs, u, i_syn, W, bias, conn, out);
}

// round 2
// speedup vs baseline: 1.0333x; 1.0333x over previous
#include <cuda_runtime.h>
#include <cstdint>

#define NN 16
#define KK 4
#define BB 16384
#define DD 64
#define FINAL_ID 15

// packed spike masks: one 64-bit mask per (node,row): bit d = (s_prev[n,b,d] != 0)
__device__ uint2 g_packed[NN * BB];

// ---------------------------------------------------------------------------
// Kernel 0: pack s_prev (binary 0/1 floats) into bitmasks. HBM-bound, ~64MB read.
// ---------------------------------------------------------------------------
__global__ void pack_kernel(const float* __restrict__ s_prev) {
    const int ROWS_PER_WARP = 8;
    int warp = (blockIdx.x * blockDim.x + threadIdx.x) >> 5;
    int lane = threadIdx.x & 31;
    int row0 = warp * ROWS_PER_WARP;
    #pragma unroll
    for (int r = 0; r < ROWS_PER_WARP; r++) {
        int row = row0 + r;
        float v0 = s_prev[(size_t)row * DD + lane];
        float v1 = s_prev[(size_t)row * DD + 32 + lane];
        unsigned lo = __ballot_sync(0xffffffffu, v0 != 0.0f);
        unsigned hi = __ballot_sync(0xffffffffu, v1 != 0.0f);
        if (lane == 0) g_packed[row] = make_uint2(lo, hi);
    }
}

// ---------------------------------------------------------------------------
// Kernel 1: fused gather + per-node Dense + LIF, register-blocked 8 rows/warp.
// grid = (NN, BB/256), block = 256 threads (8 warps). Warp owns 32 rows
// (4 groups of 8). Thread owns output dims {2*lane, 2*lane+1}.
// Dense w LDS.64 is amortized over 8 rows -> smem traffic cut ~2.7x.
// ---------------------------------------------------------------------------
__global__ __launch_bounds__(256, 2)
void snn_fused_kernel(const float* __restrict__ inputs,
                      const float* __restrict__ u,
                      const float* __restrict__ i_syn,
                      const float* __restrict__ W,
                      const float* __restrict__ bias,
                      const int*   __restrict__ conn,
                      float* __restrict__ out) {
    extern __shared__ float Wsh[];                 // [320][64] = 80 KB

    const int n    = blockIdx.x;
    const int tile = blockIdx.y;
    const int tid  = threadIdx.x;
    const int lane = tid & 31;
    const int warp = tid >> 5;

    // cooperative load of W[n] (320x64 floats) into smem, float4 vectorized
    {
        const float4* Wg  = (const float4*)(W + (size_t)n * 320 * 64);
        float4*       Ws4 = (float4*)Wsh;
        #pragma unroll
        for (int i = 0; i < 20; i++)
            Ws4[tid + i * 256] = Wg[tid + i * 256];
    }

    int src[KK];
    #pragma unroll
    for (int k = 0; k < KK; k++) src[k] = conn[n * KK + k];

    float2 bv = *(const float2*)(bias + n * DD + 2 * lane);
    __syncthreads();

    // output layout: [out (B*D)] [s_new (N*B*D)] [u_out (N*B*D)] [i_new (N*B*D)]
    float* s_out = out + (size_t)BB * DD;
    float* u_out = s_out + (size_t)NN * BB * DD;
    float* i_out = u_out + (size_t)NN * BB * DD;

    const int rowbase = tile * 256 + warp * 32;

    for (int g = 0; g < 4; g++) {
        const int b0 = rowbase + g * 8;

        float2 acc[8];
        #pragma unroll
        for (int r = 0; r < 8; r++) acc[r] = bv;

        // ---- dense block: inputs(64) @ W[256:320, :], 8 rows at once ----
        #pragma unroll
        for (int dd = 0; dd < 16; dd++) {
            float4 xv[8];
            #pragma unroll
            for (int r = 0; r < 8; r++)
                xv[r] = __ldg((const float4*)(inputs + (b0 + r) * DD + dd * 4));
            #pragma unroll
            for (int j = 0; j < 4; j++) {
                float2 w = *(const float2*)(Wsh + (256 + dd * 4 + j) * 64 + 2 * lane);
                #pragma unroll
                for (int r = 0; r < 8; r++) {
                    float x = (j == 0) ? xv[r].x :
                              (j == 1) ? xv[r].y :
                              (j == 2) ? xv[r].z : xv[r].w;
                    acc[r].x = fmaf(x, w.x, acc[r].x);
                    acc[r].y = fmaf(x, w.y, acc[r].y);
                }
            }
        }

        // ---- sparse block + LIF epilogue, per row ----
        #pragma unroll
        for (int r = 0; r < 8; r++) {
            const int b = b0 + r;
            const size_t base = ((size_t)n * BB + b) * DD + 2 * lane;
            float2 uu = *(const float2*)(u + base);
            float2 is = *(const float2*)(i_syn + base);
            float2 a = acc[r];

            #pragma unroll
            for (int k = 0; k < KK; k++) {
                uint2 m = g_packed[src[k] * BB + b];
                unsigned mm = m.x;
                while (mm) {
                    int bit = __ffs(mm) - 1;
                    mm &= mm - 1;
                    float2 w = *(const float2*)(Wsh + (k * 64 + bit) * 64 + 2 * lane);
                    a.x += w.x;
                    a.y += w.y;
                }
                mm = m.y;
                while (mm) {
                    int bit = __ffs(mm) - 1;
                    mm &= mm - 1;
                    float2 w = *(const float2*)(Wsh + (k * 64 + 32 + bit) * 64 + 2 * lane);
                    a.x += w.x;
                    a.y += w.y;
                }
            }

            // LIF update (fp32, scalar literals matching jnp weak-typed constants)
            float2 inew, unew, sv, uo;
            inew.x = fmaf(0.9f, is.x, a.x);
            inew.y = fmaf(0.9f, is.y, a.y);
            unew.x = fmaf(0.95f, uu.x, 0.05f * inew.x);
            unew.y = fmaf(0.95f, uu.y, 0.05f * inew.y);
            sv.x = (unew.x - 1.0f > 0.0f) ? 1.0f : 0.0f;
            sv.y = (unew.y - 1.0f > 0.0f) ? 1.0f : 0.0f;
            uo.x = (sv.x > 0.5f) ? 0.0f : unew.x;
            uo.y = (sv.y > 0.5f) ? 0.0f : unew.y;

            *(float2*)(s_out + base) = sv;
            *(float2*)(u_out + base) = uo;
            *(float2*)(i_out + base) = inew;
            if (n == FINAL_ID)
                *(float2*)(out + (size_t)b * DD + 2 * lane) = sv;
        }
    }
}

// ---------------------------------------------------------------------------
extern "C" void kernel_launch(void* const* d_in, const int* in_sizes, int n_in,
                              void* d_out, int out_size) {
    const float* inputs = (const float*)d_in[0];
    const float* u      = (const float*)d_in[1];
    const float* i_syn  = (const float*)d_in[2];
    const float* s_prev = (const float*)d_in[3];
    const float* W      = (const float*)d_in[4];
    const float* bias   = (const float*)d_in[5];
    const int*   conn   = (const int*)d_in[6];
    float* out = (float*)d_out;

    pack_kernel<<<(NN * BB) / 64, 256>>>(s_prev);

    const int smem = 320 * 64 * sizeof(float);     // 80 KB
    cudaFuncSetAttribute(snn_fused_kernel,
                         cudaFuncAttributeMaxDynamicSharedMemorySize, smem);

    dim3 grid(NN, BB / 256);
    snn_fused_kernel<<<grid, 256, smem>>>(inputs, u, i_syn, W, bias, conn, out);
}

// round 3
// speedup vs baseline: 1.0607x; 1.0264x over previous
#include <cuda_runtime.h>
#include <cstdint>

#define NN 16
#define KK 4
#define BB 16384
#define DD 64
#define FINAL_ID 15
#define LMAX 96   // max (padded) sparse indices per row; Binomial(256,0.1) >8 sigma safe

// packed spike masks: one 64-bit mask per (node,row): bit d = (s_prev[n,b,d] != 0)
__device__ uint2 g_packed[NN * BB];
// per-(target node, row) index lists into the 320-row W tile (u16, padded w/ 320)
__device__ uint16_t g_idx[(size_t)NN * BB * LMAX];
__device__ int g_cnt[NN * BB];

// ---------------------------------------------------------------------------
// Kernel 0: pack s_prev (binary 0/1 floats) into bitmasks. HBM-bound, ~64MB read.
// ---------------------------------------------------------------------------
__global__ void pack_kernel(const float* __restrict__ s_prev) {
    const int ROWS_PER_WARP = 8;
    int warp = (blockIdx.x * blockDim.x + threadIdx.x) >> 5;
    int lane = threadIdx.x & 31;
    int row0 = warp * ROWS_PER_WARP;
    #pragma unroll
    for (int r = 0; r < ROWS_PER_WARP; r++) {
        int row = row0 + r;
        float v0 = s_prev[(size_t)row * DD + lane];
        float v1 = s_prev[(size_t)row * DD + 32 + lane];
        unsigned lo = __ballot_sync(0xffffffffu, v0 != 0.0f);
        unsigned hi = __ballot_sync(0xffffffffu, v1 != 0.0f);
        if (lane == 0) g_packed[row] = make_uint2(lo, hi);
    }
}

// ---------------------------------------------------------------------------
// Kernel 1: build per-(target,row) sparse index lists from the masks.
// One thread per (n,b). Indices idx = k*64 + d address rows of the smem W tile.
// Padded to a multiple of 4 with idx=320 (a zeroed row).
// ---------------------------------------------------------------------------
__global__ void build_lists_kernel(const int* __restrict__ conn) {
    int t = blockIdx.x * blockDim.x + threadIdx.x;   // 0 .. NN*BB-1
    int n = t >> 14;            // /BB
    int b = t & (BB - 1);
    uint16_t* dst = g_idx + (size_t)t * LMAX;

    unsigned long long cur = 0;
    int cnt = 0;
    #pragma unroll
    for (int k = 0; k < KK; k++) {
        uint2 m = g_packed[conn[n * KK + k] * BB + b];
        #pragma unroll
        for (int w = 0; w < 2; w++) {
            unsigned mm = (w == 0) ? m.x : m.y;
            int base = k * 64 + w * 32;
            while (mm) {
                int bit = __ffs(mm) - 1;
                mm &= mm - 1;
                cur |= ((unsigned long long)(base + bit)) << (16 * (cnt & 3));
                cnt++;
                if ((cnt & 3) == 0) {
                    *(unsigned long long*)(dst + cnt - 4) = cur;
                    cur = 0;
                }
            }
        }
    }
    int rem = cnt & 3;
    if (rem) {
        #pragma unroll
        for (int p = 3; p >= 1; p--)
            if (p >= rem) cur |= 320ULL << (16 * p);
        cnt += 4 - rem;
        *(unsigned long long*)(dst + cnt - 4) = cur;
    }
    g_cnt[t] = cnt;
}

// ---------------------------------------------------------------------------
// Kernel 2: fused Dense + sparse-accumulate + LIF, register-blocked 8 rows/warp.
// grid = (NN, BB/256), block = 256 threads. Thread owns cols {2*lane, 2*lane+1}.
// ---------------------------------------------------------------------------
__global__ __launch_bounds__(256, 2)
void snn_fused_kernel(const float* __restrict__ inputs,
                      const float* __restrict__ u,
                      const float* __restrict__ i_syn,
                      const float* __restrict__ W,
                      const float* __restrict__ bias,
                      float* __restrict__ out) {
    extern __shared__ float Wsh[];                 // [321][64]; row 320 = zeros

    const int n    = blockIdx.x;
    const int tile = blockIdx.y;
    const int tid  = threadIdx.x;
    const int lane = tid & 31;
    const int warp = tid >> 5;

    // cooperative load of W[n] (320x64 floats) into smem, float4 vectorized
    {
        const float4* Wg  = (const float4*)(W + (size_t)n * 320 * 64);
        float4*       Ws4 = (float4*)Wsh;
        #pragma unroll
        for (int i = 0; i < 20; i++)
            Ws4[tid + i * 256] = Wg[tid + i * 256];
        if (tid < 16)                               // zero pad row 320
            ((float4*)(Wsh + 320 * 64))[tid] = make_float4(0.f, 0.f, 0.f, 0.f);
    }

    float2 bv = *(const float2*)(bias + n * DD + 2 * lane);
    __syncthreads();

    float* s_out = out + (size_t)BB * DD;
    float* u_out = s_out + (size_t)NN * BB * DD;
    float* i_out = u_out + (size_t)NN * BB * DD;

    const int rowbase = tile * 256 + warp * 32;

    for (int g = 0; g < 4; g++) {
        const int b0 = rowbase + g * 8;

        float2 acc[8];
        #pragma unroll
        for (int r = 0; r < 8; r++) acc[r] = bv;

        // ---- dense block: inputs(64) @ W[256:320, :], 8 rows at once ----
        #pragma unroll
        for (int dd = 0; dd < 16; dd++) {
            float4 xv[8];
            #pragma unroll
            for (int r = 0; r < 8; r++)
                xv[r] = __ldg((const float4*)(inputs + (b0 + r) * DD + dd * 4));
            #pragma unroll
            for (int j = 0; j < 4; j++) {
                float2 w = *(const float2*)(Wsh + (256 + dd * 4 + j) * 64 + 2 * lane);
                #pragma unroll
                for (int r = 0; r < 8; r++) {
                    float x = (j == 0) ? xv[r].x :
                              (j == 1) ? xv[r].y :
                              (j == 2) ? xv[r].z : xv[r].w;
                    acc[r].x = fmaf(x, w.x, acc[r].x);
                    acc[r].y = fmaf(x, w.y, acc[r].y);
                }
            }
        }

        // ---- sparse block (indexed, counted, x4 unrolled) + LIF per row ----
        #pragma unroll
        for (int r = 0; r < 8; r++) {
            const int b = b0 + r;
            const int row = n * BB + b;
            const size_t base = ((size_t)row) * DD + 2 * lane;
            float2 uu = *(const float2*)(u + base);
            float2 is = *(const float2*)(i_syn + base);

            const uint16_t* lp = g_idx + (size_t)row * LMAX;
            const int cnt = g_cnt[row];

            float2 a  = acc[r];
            float2 a2 = make_float2(0.f, 0.f);
            for (int i = 0; i < cnt; i += 4) {
                ushort4 q = *(const ushort4*)(lp + i);
                float2 w0 = *(const float2*)(Wsh + q.x * 64 + 2 * lane);
                float2 w1 = *(const float2*)(Wsh + q.y * 64 + 2 * lane);
                float2 w2 = *(const float2*)(Wsh + q.z * 64 + 2 * lane);
                float2 w3 = *(const float2*)(Wsh + q.w * 64 + 2 * lane);
                a.x  += w0.x;  a.y  += w0.y;
                a2.x += w1.x;  a2.y += w1.y;
                a.x  += w2.x;  a.y  += w2.y;
                a2.x += w3.x;  a2.y += w3.y;
            }
            a.x += a2.x;
            a.y += a2.y;

            // LIF update (fp32, scalar literals matching jnp weak-typed constants)
            float2 inew, unew, sv, uo;
            inew.x = fmaf(0.9f, is.x, a.x);
            inew.y = fmaf(0.9f, is.y, a.y);
            unew.x = fmaf(0.95f, uu.x, 0.05f * inew.x);
            unew.y = fmaf(0.95f, uu.y, 0.05f * inew.y);
            sv.x = (unew.x - 1.0f > 0.0f) ? 1.0f : 0.0f;
            sv.y = (unew.y - 1.0f > 0.0f) ? 1.0f : 0.0f;
            uo.x = (sv.x > 0.5f) ? 0.0f : unew.x;
            uo.y = (sv.y > 0.5f) ? 0.0f : unew.y;

            *(float2*)(s_out + base) = sv;
            *(float2*)(u_out + base) = uo;
            *(float2*)(i_out + base) = inew;
            if (n == FINAL_ID)
                *(float2*)(out + (size_t)b * DD + 2 * lane) = sv;
        }
    }
}

// ---------------------------------------------------------------------------
extern "C" void kernel_launch(void* const* d_in, const int* in_sizes, int n_in,
                              void* d_out, int out_size) {
    const float* inputs = (const float*)d_in[0];
    const float* u      = (const float*)d_in[1];
    const float* i_syn  = (const float*)d_in[2];
    const float* s_prev = (const float*)d_in[3];
    const float* W      = (const float*)d_in[4];
    const float* bias   = (const float*)d_in[5];
    const int*   conn   = (const int*)d_in[6];
    float* out = (float*)d_out;

    pack_kernel<<<(NN * BB) / 64, 256>>>(s_prev);
    build_lists_kernel<<<(NN * BB) / 256, 256>>>(conn);

    const int smem = 321 * 64 * sizeof(float);     // 80.25 KB (incl. zero row)
    cudaFuncSetAttribute(snn_fused_kernel,
                         cudaFuncAttributeMaxDynamicSharedMemorySize, smem);

    dim3 grid(NN, BB / 256);
    snn_fused_kernel<<<grid, 256, smem>>>(inputs, u, i_syn, W, bias, out);
}

// round 4
// speedup vs baseline: 1.3205x; 1.2450x over previous
#include <cuda_runtime.h>
#include <cstdint>

#define NN 16
#define KK 4
#define BB 16384
#define DD 64
#define FINAL_ID 15
#define LMAX 96   // max (padded) sparse indices per row; Binomial(256,0.1) >8 sigma safe

// packed spike masks: one 64-bit mask per (node,row): bit d = (s_prev[n,b,d] != 0)
__device__ uint2 g_packed[NN * BB];
// per-(target node, row) index lists into the 320-row W tile (u16, padded w/ 320)
__device__ uint16_t g_idx[(size_t)NN * BB * LMAX];
__device__ int g_cnt[NN * BB];

// ---------------------------------------------------------------------------
// Kernel 0: pack s_prev (binary 0/1 floats) into bitmasks.
// ---------------------------------------------------------------------------
__global__ void pack_kernel(const float* __restrict__ s_prev) {
    const int ROWS_PER_WARP = 8;
    int warp = (blockIdx.x * blockDim.x + threadIdx.x) >> 5;
    int lane = threadIdx.x & 31;
    int row0 = warp * ROWS_PER_WARP;
    #pragma unroll
    for (int r = 0; r < ROWS_PER_WARP; r++) {
        int row = row0 + r;
        float v0 = s_prev[(size_t)row * DD + lane];
        float v1 = s_prev[(size_t)row * DD + 32 + lane];
        unsigned lo = __ballot_sync(0xffffffffu, v0 != 0.0f);
        unsigned hi = __ballot_sync(0xffffffffu, v1 != 0.0f);
        if (lane == 0) g_packed[row] = make_uint2(lo, hi);
    }
}

// ---------------------------------------------------------------------------
// Kernel 1: build per-(target,row) sparse index lists from the masks.
// ---------------------------------------------------------------------------
__global__ void build_lists_kernel(const int* __restrict__ conn) {
    int t = blockIdx.x * blockDim.x + threadIdx.x;   // 0 .. NN*BB-1
    int n = t >> 14;            // /BB
    int b = t & (BB - 1);
    uint16_t* dst = g_idx + (size_t)t * LMAX;

    unsigned long long cur = 0;
    int cnt = 0;
    #pragma unroll
    for (int k = 0; k < KK; k++) {
        uint2 m = g_packed[conn[n * KK + k] * BB + b];
        #pragma unroll
        for (int w = 0; w < 2; w++) {
            unsigned mm = (w == 0) ? m.x : m.y;
            int base = k * 64 + w * 32;
            while (mm) {
                int bit = __ffs(mm) - 1;
                mm &= mm - 1;
                cur |= ((unsigned long long)(base + bit)) << (16 * (cnt & 3));
                cnt++;
                if ((cnt & 3) == 0) {
                    *(unsigned long long*)(dst + cnt - 4) = cur;
                    cur = 0;
                }
            }
        }
    }
    int rem = cnt & 3;
    if (rem) {
        #pragma unroll
        for (int p = 3; p >= 1; p--)
            if (p >= rem) cur |= 320ULL << (16 * p);
        cnt += 4 - rem;
        *(unsigned long long*)(dst + cnt - 4) = cur;
    }
    g_cnt[t] = cnt;
}

// packed f32x2 add (bit-identical to two scalar IEEE adds)
__device__ __forceinline__ void addx2(unsigned long long& a, unsigned long long w) {
    asm("add.rn.f32x2 %0, %0, %1;" : "+l"(a) : "l"(w));
}

// ---------------------------------------------------------------------------
// Kernel 2: fused Dense + sparse-accumulate + LIF.
// 512-thread blocks (16 warps), 2 blocks/SM -> 32 warps/SM (50% occ).
// grid = (NN, 64): block covers 256 batch rows; warp owns 16 rows (4 groups
// of 4, register-blocked). Thread owns output cols {2*lane, 2*lane+1}.
// ---------------------------------------------------------------------------
__global__ __launch_bounds__(512, 2)
void snn_fused_kernel(const float* __restrict__ inputs,
                      const float* __restrict__ u,
                      const float* __restrict__ i_syn,
                      const float* __restrict__ W,
                      const float* __restrict__ bias,
                      float* __restrict__ out) {
    extern __shared__ float Wsh[];                 // [321][64]; row 320 = zeros

    const int n    = blockIdx.x;
    const int tile = blockIdx.y;
    const int tid  = threadIdx.x;
    const int lane = tid & 31;
    const int warp = tid >> 5;

    // cooperative load of W[n] (320x64 floats) into smem, float4 vectorized
    {
        const float4* Wg  = (const float4*)(W + (size_t)n * 320 * 64);
        float4*       Ws4 = (float4*)Wsh;
        #pragma unroll
        for (int i = 0; i < 10; i++)
            Ws4[tid + i * 512] = Wg[tid + i * 512];
        if (tid < 16)                               // zero pad row 320
            ((float4*)(Wsh + 320 * 64))[tid] = make_float4(0.f, 0.f, 0.f, 0.f);
    }

    float2 bv = *(const float2*)(bias + n * DD + 2 * lane);
    __syncthreads();

    float* s_out = out + (size_t)BB * DD;
    float* u_out = s_out + (size_t)NN * BB * DD;
    float* i_out = u_out + (size_t)NN * BB * DD;

    const int rowbase = tile * 256 + warp * 16;

    for (int g = 0; g < 4; g++) {
        const int b0 = rowbase + g * 4;

        float2 acc[4];
        #pragma unroll
        for (int r = 0; r < 4; r++) acc[r] = bv;

        // ---- dense block: inputs(64) @ W[256:320, :], 4 rows at once ----
        #pragma unroll
        for (int dd = 0; dd < 16; dd++) {
            float4 xv[4];
            #pragma unroll
            for (int r = 0; r < 4; r++)
                xv[r] = __ldg((const float4*)(inputs + (b0 + r) * DD + dd * 4));
            #pragma unroll
            for (int j = 0; j < 4; j++) {
                float2 w = *(const float2*)(Wsh + (256 + dd * 4 + j) * 64 + 2 * lane);
                #pragma unroll
                for (int r = 0; r < 4; r++) {
                    float x = (j == 0) ? xv[r].x :
                              (j == 1) ? xv[r].y :
                              (j == 2) ? xv[r].z : xv[r].w;
                    acc[r].x = fmaf(x, w.x, acc[r].x);
                    acc[r].y = fmaf(x, w.y, acc[r].y);
                }
            }
        }

        // ---- sparse block (indexed, counted, x4 unrolled, packed adds) ----
        #pragma unroll
        for (int r = 0; r < 4; r++) {
            const int b = b0 + r;
            const int row = n * BB + b;
            const size_t base = ((size_t)row) * DD + 2 * lane;
            float2 uu = *(const float2*)(u + base);
            float2 is = *(const float2*)(i_syn + base);

            const uint16_t* lp = g_idx + (size_t)row * LMAX;
            const int cnt = g_cnt[row];

            unsigned long long a, a2 = 0;
            { float2 t0 = acc[r]; a = *(unsigned long long*)&t0; }

            for (int i = 0; i < cnt; i += 4) {
                ushort4 q = *(const ushort4*)(lp + i);
                unsigned long long w0 = *(const unsigned long long*)(Wsh + q.x * 64 + 2 * lane);
                unsigned long long w1 = *(const unsigned long long*)(Wsh + q.y * 64 + 2 * lane);
                unsigned long long w2 = *(const unsigned long long*)(Wsh + q.z * 64 + 2 * lane);
                unsigned long long w3 = *(const unsigned long long*)(Wsh + q.w * 64 + 2 * lane);
                addx2(a,  w0);
                addx2(a2, w1);
                addx2(a,  w2);
                addx2(a2, w3);
            }
            addx2(a, a2);
            float2 av = *(float2*)&a;

            // LIF update (fp32, scalar literals matching jnp weak-typed constants)
            float2 inew, unew, sv, uo;
            inew.x = fmaf(0.9f, is.x, av.x);
            inew.y = fmaf(0.9f, is.y, av.y);
            unew.x = fmaf(0.95f, uu.x, 0.05f * inew.x);
            unew.y = fmaf(0.95f, uu.y, 0.05f * inew.y);
            sv.x = (unew.x - 1.0f > 0.0f) ? 1.0f : 0.0f;
            sv.y = (unew.y - 1.0f > 0.0f) ? 1.0f : 0.0f;
            uo.x = (sv.x > 0.5f) ? 0.0f : unew.x;
            uo.y = (sv.y > 0.5f) ? 0.0f : unew.y;

            *(float2*)(s_out + base) = sv;
            *(float2*)(u_out + base) = uo;
            *(float2*)(i_out + base) = inew;
            if (n == FINAL_ID)
                *(float2*)(out + (size_t)b * DD + 2 * lane) = sv;
        }
    }
}

// ---------------------------------------------------------------------------
extern "C" void kernel_launch(void* const* d_in, const int* in_sizes, int n_in,
                              void* d_out, int out_size) {
    const float* inputs = (const float*)d_in[0];
    const float* u      = (const float*)d_in[1];
    const float* i_syn  = (const float*)d_in[2];
    const float* s_prev = (const float*)d_in[3];
    const float* W      = (const float*)d_in[4];
    const float* bias   = (const float*)d_in[5];
    const int*   conn   = (const int*)d_in[6];
    float* out = (float*)d_out;

    pack_kernel<<<(NN * BB) / 64, 256>>>(s_prev);
    build_lists_kernel<<<(NN * BB) / 256, 256>>>(conn);

    const int smem = 321 * 64 * sizeof(float);     // ~80.3 KB (incl. zero row)
    cudaFuncSetAttribute(snn_fused_kernel,
                         cudaFuncAttributeMaxDynamicSharedMemorySize, smem);

    dim3 grid(NN, BB / 256);
    snn_fused_kernel<<<grid, 512, smem>>>(inputs, u, i_syn, W, bias, out);
}